// round 5
// baseline (speedup 1.0000x reference)
#include <cuda_runtime.h>
#include <cstdint>

// Embedding backward (scatter-add).
//   d_in[0]: grad_output, float32, [B*S, 128]   (B*S = 131072)
//   d_in[1]: indices,     int32,   [B*S]
//   d_out  : float32 [200000, 128]; segment_sum skipping index==0.
//
// Strategy: the 102.4 MB output table nearly fits in the ~126 MB L2.
//   1) zero_table with NORMAL stores -> zeros become L2-resident (no DRAM
//      round-trip; writeback deferred and usually overwritten next replay).
//   2) scatter with red.global.add.v4.f32 -> RMW hits L2-resident lines.
//      grad is read with __ldcs (evict-first) so the 64 MB stream does not
//      evict the table from L2.

static constexpr int D  = 128;
static constexpr int D4 = D / 4;   // 32 float4s per row = one warp

// ---------------------------------------------------------------------------
// Kernel 1: zero the table. Normal stores -> write-allocate into L2.
// One float4 per thread, exact grid.
// ---------------------------------------------------------------------------
__global__ void __launch_bounds__(256) zero_table_kernel(float4* __restrict__ out,
                                                         long long n4) {
    long long i = (long long)blockIdx.x * blockDim.x + threadIdx.x;
    if (i < n4) {
        out[i] = make_float4(0.f, 0.f, 0.f, 0.f);  // default: L2 write-allocate
    }
}

// ---------------------------------------------------------------------------
// Kernel 2: warp-per-row scatter-add via vector RED.
// ---------------------------------------------------------------------------
__global__ void __launch_bounds__(256) scatter_add_kernel(
    const float4* __restrict__ grad,   // [rows, 32] as float4
    const int* __restrict__ indices,   // [rows]
    float* __restrict__ out,           // [V, 128]
    int rows)
{
    int warp = (blockIdx.x * blockDim.x + threadIdx.x) >> 5;
    int lane = threadIdx.x & 31;
    if (warp >= rows) return;

    int e = __ldg(&indices[warp]);
    if (e == 0) return;  // PADDING_IDX — uniform across warp

    // Streaming (evict-first) read: don't let the 64 MB grad stream evict
    // the L2-resident output table.
    float4 g = __ldcs(&grad[(long long)warp * D4 + lane]);

    float* dst = out + (long long)e * D + lane * 4;
    asm volatile(
        "red.global.add.v4.f32 [%0], {%1, %2, %3, %4};"
        :
        : "l"(dst), "f"(g.x), "f"(g.y), "f"(g.z), "f"(g.w)
        : "memory");
}

// ---------------------------------------------------------------------------
extern "C" void kernel_launch(void* const* d_in, const int* in_sizes, int n_in,
                              void* d_out, int out_size) {
    const float4* grad = (const float4*)d_in[0];
    const int* indices = (const int*)d_in[1];
    float* out         = (float*)d_out;

    const int rows = in_sizes[1];                  // B*S
    const long long n4 = (long long)out_size / 4;  // output float4 count

    // Zero the table into L2.
    {
        int threads = 256;
        long long blocks = (n4 + threads - 1) / threads;  // 25600 for 200k x 128
        zero_table_kernel<<<(int)blocks, threads>>>((float4*)out, n4);
    }

    // Scatter-add: one warp per row.
    {
        int threads = 256;  // 8 warps/CTA
        int blocks = (rows + (threads / 32) - 1) / (threads / 32);
        scatter_add_kernel<<<blocks, threads>>>(grad, indices, out, rows);
    }
}